// round 11
// baseline (speedup 1.0000x reference)
#include <cuda_runtime.h>
#include <stdint.h>
#include <math.h>

// ---------------------------------------------------------------------------
// out[b,o] = min_i ( x[b,i] + mask[o,i] ),  B=IN=OUT=512,  x in [0,1)
// mask in {0,1}  =>  out[b,o] = min over SELECTED i of x[b,i]  (sparse min).
// Selection = JAX threefry bernoulli (partitionable variant, validated R2-R10).
// Single persistent kernel: mask + sort -> grid barrier -> gather.
// ---------------------------------------------------------------------------

#define B_DIM   512
#define IN_DIM  512
#define OUT_DIM 512
#define NBLK    512u

// column-major selection bitmask: bit o%32 of g_selC[(o>>5)*512 + i]
__device__ uint32_t g_selC[16 * IN_DIM];
__device__ unsigned g_bar;        // monotonic epoch counter (never reset)

// ---------------- Threefry-2x32 (constexpr) --------------------------------
struct TF2 { uint32_t a, b; };

__host__ __device__ constexpr uint32_t rotl32(uint32_t v, int r) {
    return (v << r) | (v >> (32 - r));
}

__host__ __device__ constexpr TF2 tf2x32(uint32_t k0, uint32_t k1,
                                         uint32_t x0, uint32_t x1) {
    uint32_t k2 = k0 ^ k1 ^ 0x1BD11BDAu;
    x0 += k0; x1 += k1;
    x0 += x1; x1 = rotl32(x1, 13) ^ x0;
    x0 += x1; x1 = rotl32(x1, 15) ^ x0;
    x0 += x1; x1 = rotl32(x1, 26) ^ x0;
    x0 += x1; x1 = rotl32(x1,  6) ^ x0;
    x0 += k1; x1 += k2 + 1u;
    x0 += x1; x1 = rotl32(x1, 17) ^ x0;
    x0 += x1; x1 = rotl32(x1, 29) ^ x0;
    x0 += x1; x1 = rotl32(x1, 16) ^ x0;
    x0 += x1; x1 = rotl32(x1, 24) ^ x0;
    x0 += k2; x1 += k0 + 2u;
    x0 += x1; x1 = rotl32(x1, 13) ^ x0;
    x0 += x1; x1 = rotl32(x1, 15) ^ x0;
    x0 += x1; x1 = rotl32(x1, 26) ^ x0;
    x0 += x1; x1 = rotl32(x1,  6) ^ x0;
    x0 += k0; x1 += k1 + 3u;
    x0 += x1; x1 = rotl32(x1, 17) ^ x0;
    x0 += x1; x1 = rotl32(x1, 29) ^ x0;
    x0 += x1; x1 = rotl32(x1, 16) ^ x0;
    x0 += x1; x1 = rotl32(x1, 24) ^ x0;
    x0 += k1; x1 += k2 + 4u;
    x0 += x1; x1 = rotl32(x1, 13) ^ x0;
    x0 += x1; x1 = rotl32(x1, 15) ^ x0;
    x0 += x1; x1 = rotl32(x1, 26) ^ x0;
    x0 += x1; x1 = rotl32(x1,  6) ^ x0;
    x0 += k2; x1 += k0 + 5u;
    return TF2{x0, x1};
}

constexpr TF2 KB = tf2x32(0u, 42u, 0u, 0u);   // k_bern (foldlike split of key 42)

// ---------------- bernoulli decision (validated) -----------------------------
__device__ __forceinline__ bool edge_selected(const float2 w, uint32_t n) {
    TF2 r = tf2x32(KB.a, KB.b, 0u, n);
    uint32_t bits = r.a ^ r.b;
    float u = __uint_as_float((bits >> 9) | 0x3F800000u) - 1.0f;
    float t = u * (1.0f + __expf(w.x - w.y));
    if (t < 1.0f - 1e-5f) return true;
    if (t > 1.0f + 1e-5f) return false;
    double e = exp((double)w.x - (double)w.y);       // boundary: exact fp64
    return ((double)u) * (1.0 + e) < 1.0;
}

// ---------------- bitonic helpers (2 elems/thread: e0=2t, e1=2t+1) ----------
#define BSWAP(A, PA, KEEPMIN) ((KEEPMIN) ? umin((A),(PA)) : umax((A),(PA)))

#define STAGE_J1(K) {                                                         \
    bool dir = (((2*t) & (K)) == 0);                                          \
    uint32_t lo = umin(a, b), hi = umax(a, b);                                \
    a = dir ? lo : hi; b = dir ? hi : lo; }

#define STAGE_SHFL(J, K) {                                                    \
    uint32_t pa = __shfl_xor_sync(0xFFFFFFFFu, a, (J) >> 1);                  \
    uint32_t pb = __shfl_xor_sync(0xFFFFFFFFu, b, (J) >> 1);                  \
    bool dir = (((2*t) & (K)) == 0);                                          \
    bool lower = ((t & ((J) >> 1)) == 0);                                     \
    bool km = (dir == lower);                                                 \
    a = BSWAP(a, pa, km); b = BSWAP(b, pb, km); }

#define STAGE_SMEM(J, K) {                                                    \
    __syncthreads();                                                          \
    sk[2*t] = a; sk[2*t+1] = b;                                               \
    __syncthreads();                                                          \
    uint32_t pa = sk[(2*t) ^ (J)];                                            \
    uint32_t pb = sk[(2*t+1) ^ (J)];                                          \
    bool dir = (((2*t) & (K)) == 0);                                          \
    bool lower = (((2*t) & (J)) == 0);                                        \
    bool km = (dir == lower);                                                 \
    a = BSWAP(a, pa, km); b = BSWAP(b, pb, km); }

#define TAIL32(K) STAGE_SHFL(32,K) STAGE_SHFL(16,K) STAGE_SHFL(8,K) \
                  STAGE_SHFL(4,K)  STAGE_SHFL(2,K)  STAGE_J1(K)

// 5-step butterfly 32x32 bit-matrix transpose across lanes
#define TSTEP(V, K, M) {                                                      \
    uint32_t y_ = __shfl_xor_sync(0xFFFFFFFFu, V, K);                         \
    V = (lane & (K)) ? ((V & (M)) | ((y_ >> (K)) & ~(M)))                     \
                     : ((V & ~(M)) | ((y_ << (K)) & (M))); }

#define TRANSPOSE32(V) TSTEP(V, 16, 0xFFFF0000u) TSTEP(V, 8, 0xFF00FF00u)     \
                       TSTEP(V, 4,  0xF0F0F0F0u) TSTEP(V, 2, 0xCCCCCCCCu)     \
                       TSTEP(V, 1,  0xAAAAAAAAu)

// ---------------- fused persistent kernel -----------------------------------
__global__ __launch_bounds__(256, 4) void fused_kernel(
    const float* __restrict__ x, const float* __restrict__ pw,
    float* __restrict__ out) {
    __shared__ uint32_t sk[512];
    __shared__ float    s_xv[512];
    __shared__ uint32_t s_ti[64];
    __shared__ float    s_tv[64];
    __shared__ unsigned s_tgt;

    const int t   = threadIdx.x;
    const int bid = blockIdx.x;
    const int lane = t & 31;
    const uint32_t wrp = (uint32_t)t >> 5;           // 0..7

    // ======== Phase A: mask, 512 edges for (ow = bid&15, i in [ib,ib+16)) ===
    {
        const uint32_t ow = (uint32_t)bid & 15u;
        const uint32_t ib = ((uint32_t)bid >> 4) * 16u;
        const uint32_t o  = ow * 32u + lane;
        const uint32_t i0 = ib + wrp;
        const uint32_t i1 = ib + wrp + 8u;
        const uint32_t n0 = o * 512u + i0;
        const uint32_t n1 = o * 512u + i1;
        float2 w0 = reinterpret_cast<const float2*>(pw)[n0];
        float2 w1 = reinterpret_cast<const float2*>(pw)[n1];
        bool s0 = edge_selected(w0, n0);
        bool s1 = edge_selected(w1, n1);
        uint32_t m0 = __ballot_sync(0xFFFFFFFFu, s0);
        uint32_t m1 = __ballot_sync(0xFFFFFFFFu, s1);
        if (lane == 0) {
            g_selC[ow * 512u + i0] = m0;
            g_selC[ow * 512u + i1] = m1;
        }
    }

    // ======== Phase B: bitonic sort of x-row bid (2 keys/thread) ============
    {
        float2 xv = reinterpret_cast<const float2*>(x + bid * IN_DIM)[t];
        s_xv[2*t]   = xv.x;
        s_xv[2*t+1] = xv.y;
        uint32_t a = ((__float_as_uint(xv.x) >> 7) << 9) | (uint32_t)(2*t);
        uint32_t b = ((__float_as_uint(xv.y) >> 7) << 9) | (uint32_t)(2*t+1);

        STAGE_J1(2)
        STAGE_SHFL(2,4)  STAGE_J1(4)
        STAGE_SHFL(4,8)  STAGE_SHFL(2,8)  STAGE_J1(8)
        STAGE_SHFL(8,16) STAGE_SHFL(4,16) STAGE_SHFL(2,16) STAGE_J1(16)
        STAGE_SHFL(16,32) STAGE_SHFL(8,32) STAGE_SHFL(4,32) STAGE_SHFL(2,32) STAGE_J1(32)
        STAGE_SHFL(32,64) STAGE_SHFL(16,64) STAGE_SHFL(8,64) STAGE_SHFL(4,64)
        STAGE_SHFL(2,64)  STAGE_J1(64)
        STAGE_SMEM(64,128)  TAIL32(128)
        STAGE_SMEM(128,256) STAGE_SMEM(64,256) TAIL32(256)
        STAGE_SMEM(256,512) STAGE_SMEM(128,512) STAGE_SMEM(64,512) TAIL32(512)

        if (t < 32) {                  // sorted elems 0..63 stay in smem only
            uint32_t ia = a & 511u, ib2 = b & 511u;
            s_ti[2*t]   = ia;   s_tv[2*t]   = s_xv[ia];
            s_ti[2*t+1] = ib2;  s_tv[2*t+1] = s_xv[ib2];
        }
    }

    // ======== grid barrier (all co-resident: 512 blocks <= 148*4) ===========
    __syncthreads();
    if (t == 0) {
        __threadfence();
        unsigned arr = atomicAdd(&g_bar, 1u);
        s_tgt = (arr / NBLK + 1u) * NBLK;
    }
    __syncthreads();
    if (t == 0) {
        unsigned tgt = s_tgt, v;
        for (;;) {
            asm volatile("ld.global.acquire.gpu.u32 %0, [%1];"
                         : "=r"(v) : "l"(&g_bar));
            if (v >= tgt) break;
            __nanosleep(64);
        }
    }
    __syncthreads();

    // ======== Phase C: gather for b = bid; warp w -> ow = w and w+8 =========
    {
        const uint32_t ow0 = wrp, ow1 = wrp + 8u;
        uint32_t idx = s_ti[lane];                    // candidate lane
        float    val = s_tv[lane];
        uint32_t m0 = g_selC[ow0 * 512u + idx];       // scattered, L2/L1
        uint32_t m1 = g_selC[ow1 * 512u + idx];
        TRANSPOSE32(m0)
        TRANSPOSE32(m1)
        bool ok0 = (m0 != 0), ok1 = (m1 != 0);
        float r0 = __shfl_sync(0xFFFFFFFFu, val, ok0 ? (__ffs(m0) - 1) : 0);
        float r1 = __shfl_sync(0xFFFFFFFFu, val, ok1 ? (__ffs(m1) - 1) : 0);

        if (!__all_sync(0xFFFFFFFFu, ok0 && ok1)) {   // P ~ 2.6e-3 per warp
            uint32_t idx2 = s_ti[32 + lane];
            float    val2 = s_tv[32 + lane];
            uint32_t n0 = g_selC[ow0 * 512u + idx2];
            uint32_t n1 = g_selC[ow1 * 512u + idx2];
            TRANSPOSE32(n0)
            TRANSPOSE32(n1)
            float q0 = __shfl_sync(0xFFFFFFFFu, val2, n0 ? (__ffs(n0) - 1) : 0);
            float q1 = __shfl_sync(0xFFFFFFFFu, val2, n1 ? (__ffs(n1) - 1) : 0);
            if (!ok0 && n0) { r0 = q0; ok0 = true; }
            if (!ok1 && n1) { r1 = q1; ok1 = true; }

            if (!ok0 || !ok1) {                       // P ~ 1e-9: exact dense
                float b0 = INFINITY, b1 = INFINITY, ball = INFINITY;
                for (int i = 0; i < IN_DIM; ++i) {
                    float v = s_xv[i];
                    ball = fminf(ball, v);
                    if ((g_selC[ow0 * 512u + i] >> lane) & 1u) b0 = fminf(b0, v);
                    if ((g_selC[ow1 * 512u + i] >> lane) & 1u) b1 = fminf(b1, v);
                }
                if (!ok0) r0 = isinf(b0) ? ball + 1.0f : b0;
                if (!ok1) r1 = isinf(b1) ? ball + 1.0f : b1;
            }
        }

        out[bid * OUT_DIM + ow0 * 32u + lane] = r0;   // coalesced
        out[bid * OUT_DIM + ow1 * 32u + lane] = r1;
    }
}

// ---------------------------------------------------------------------------
extern "C" void kernel_launch(void* const* d_in, const int* in_sizes, int n_in,
                              void* d_out, int out_size) {
    const float* x  = (const float*)d_in[0];   // [512, 512]
    const float* pw = (const float*)d_in[1];   // [512, 512, 2]
    float* out      = (float*)d_out;           // [512, 512]

    fused_kernel<<<NBLK, 256>>>(x, pw, out);
}